// round 6
// baseline (speedup 1.0000x reference)
#include <cuda_runtime.h>
#include <cuda_bf16.h>
#include <cstdint>
#include <math.h>

// ---------------------------------------------------------------------------
// Problem constants
// ---------------------------------------------------------------------------
#define S_LEN   2048
#define HIDDEN  3072
#define NH      32        // query heads
#define NHK     8         // kv heads
#define GQ      4         // H / HK
#define HD      96        // head dim
#define BLK     64        // attention block size
#define NB      32        // S / BLK
#define GH      128       // gate hidden
#define OP      4608      // H*D + 2*HK*D
#define KOFF    3072
#define VOFF    3840
#define K2H     (HIDDEN / 2)   // 1536 packed-k words

// ---------------------------------------------------------------------------
// Scratch (device globals; no allocation allowed)
// ---------------------------------------------------------------------------
__device__ float g_qkv [S_LEN * OP];          // raw qkv (pre-rope)
__device__ float g_q   [S_LEN * NH  * HD];    // roped q
__device__ float g_k   [S_LEN * NHK * HD];    // roped k
__device__ float g_qpool[NB * NHK * HD];
__device__ float g_kpool[NB * NHK * 2 * HD];
__device__ float g_qgate[NB * NHK * GH];
__device__ float g_kgate[NB * NHK * GH];
__device__ int   g_maskbuf[NHK * NB * NB];

// bf16 hi/lo packed operands (k-pairs packed into one uint32)
__device__ uint32_t g_ah [S_LEN * K2H];       // A hi (hs, then attn out)
__device__ uint32_t g_al [S_LEN * K2H];       // A lo
__device__ uint32_t g_wqh[K2H * OP];
__device__ uint32_t g_wql[K2H * OP];
__device__ uint32_t g_woh[K2H * HIDDEN];
__device__ uint32_t g_wol[K2H * HIDDEN];

// ---------------------------------------------------------------------------
// bf16 hi/lo split helpers
// ---------------------------------------------------------------------------
__device__ __forceinline__ void bsplit(float x, uint32_t& h, uint32_t& l)
{
    __nv_bfloat16 hb = __float2bfloat16(x);
    float hf = __bfloat162float(hb);
    __nv_bfloat16 lb = __float2bfloat16(x - hf);
    h = (uint32_t)__bfloat16_as_ushort(hb);
    l = (uint32_t)__bfloat16_as_ushort(lb);
}

__device__ __forceinline__ void split1(float x, uint16_t& h, uint16_t& l)
{
    __nv_bfloat16 hb = __float2bfloat16(x);
    h = __bfloat16_as_ushort(hb);
    l = __bfloat16_as_ushort(__float2bfloat16(x - __bfloat162float(hb)));
}

__device__ __forceinline__ uint32_t split2(float x, float y, uint32_t& lo)
{
    __nv_bfloat16 hx = __float2bfloat16(x), hy = __float2bfloat16(y);
    float rx = x - __bfloat162float(hx), ry = y - __bfloat162float(hy);
    __nv_bfloat16 lx = __float2bfloat16(rx), ly = __float2bfloat16(ry);
    lo = (uint32_t)__bfloat16_as_ushort(lx) | ((uint32_t)__bfloat16_as_ushort(ly) << 16);
    return (uint32_t)__bfloat16_as_ushort(hx) | ((uint32_t)__bfloat16_as_ushort(hy) << 16);
}

// Pack A (row-major M x K): word i = (x[2i], x[2i+1]) along k
__global__ void packA_kernel(const float* __restrict__ in,
                             uint32_t* __restrict__ hi, uint32_t* __restrict__ lo,
                             int total2)
{
    int i = blockIdx.x * blockDim.x + threadIdx.x;
    if (i >= total2) return;
    float2 v = ((const float2*)in)[i];
    uint32_t h0, l0, h1, l1;
    bsplit(v.x, h0, l0);
    bsplit(v.y, h1, l1);
    hi[i] = h0 | (h1 << 16);
    lo[i] = l0 | (l1 << 16);
}

// Pack B (row-major K x N): out[k2][n] = (B[2k2][n], B[2k2+1][n])
__global__ void packB_kernel(const float* __restrict__ in,
                             uint32_t* __restrict__ hi, uint32_t* __restrict__ lo,
                             int N, int total)
{
    int i = blockIdx.x * blockDim.x + threadIdx.x;
    if (i >= total) return;
    int k2 = i / N, n = i - k2 * N;
    float x0 = in[(size_t)(2 * k2) * N + n];
    float x1 = in[(size_t)(2 * k2 + 1) * N + n];
    uint32_t h0, l0, h1, l1;
    bsplit(x0, h0, l0);
    bsplit(x1, h1, l1);
    hi[i] = h0 | (h1 << 16);
    lo[i] = l0 | (l1 << 16);
}

// ---------------------------------------------------------------------------
// bf16x3 tensor-core GEMM, ldmatrix edition.
// A smem: [m][k] bf16, row stride 24 elems (48B, odd # of 16B units).
// B smem: [k][n] bf16, row stride 136 elems (272B, odd # of 16B units),
//         loaded with ldmatrix.x4.trans.
// 128x128 tile, BK=16, 256 threads, warp tile 64x32, 3 MMAs (hi*hi+hi*lo+lo*hi).
// ---------------------------------------------------------------------------
#define ASTR 24
#define BSTR 136

#define LDSM4(R0, R1, R2, R3, ADDR)                                            \
    asm volatile("ldmatrix.sync.aligned.m8n8.x4.shared.b16 {%0,%1,%2,%3}, [%4];" \
                 : "=r"(R0), "=r"(R1), "=r"(R2), "=r"(R3) : "r"(ADDR))

#define LDSM4T(R0, R1, R2, R3, ADDR)                                           \
    asm volatile("ldmatrix.sync.aligned.m8n8.x4.trans.shared.b16 {%0,%1,%2,%3}, [%4];" \
                 : "=r"(R0), "=r"(R1), "=r"(R2), "=r"(R3) : "r"(ADDR))

#define MMA_BF16(CC, A0, A1, A2, A3, B0, B1)                                   \
    asm volatile(                                                              \
        "mma.sync.aligned.m16n8k16.row.col.f32.bf16.bf16.f32 "                 \
        "{%0,%1,%2,%3}, {%4,%5,%6,%7}, {%8,%9}, {%0,%1,%2,%3};"                \
        : "+f"(CC[0]), "+f"(CC[1]), "+f"(CC[2]), "+f"(CC[3])                   \
        : "r"(A0), "r"(A1), "r"(A2), "r"(A3), "r"(B0), "r"(B1))

__global__ __launch_bounds__(256, 2)
void bf16x3_gemm(const uint32_t* __restrict__ Agh, const uint32_t* __restrict__ Agl,
                 const uint32_t* __restrict__ Bgh, const uint32_t* __restrict__ Bgl,
                 float* __restrict__ C, int M, int N, int K2)
{
    __shared__ __align__(16) uint16_t Ah[2][128 * ASTR], Al[2][128 * ASTR];
    __shared__ __align__(16) uint16_t Bh[2][16 * BSTR],  Bl[2][16 * BSTR];

    const int tid  = threadIdx.x;
    const int bn   = blockIdx.x, bm = blockIdx.y;
    const int warp = tid >> 5,  lane = tid & 31;
    const int wm   = warp >> 2, wn   = warp & 3;
    const int gid  = lane >> 2, tig  = lane & 3;

    // Global load mapping
    const int a_r = tid >> 1, a_c = (tid & 1);       // 128 rows x 2 uint4
    const int b_r = tid >> 5;                        // k2 row 0..7
    const int b_n = (lane) * 4;                      // n word offset (1 word = 1 n)

    const uint32_t* Aph = Agh + (size_t)(bm * 128 + a_r) * K2 + a_c * 4;
    const uint32_t* Apl = Agl + (size_t)(bm * 128 + a_r) * K2 + a_c * 4;
    const uint32_t* Bph = Bgh + (size_t)b_r * N + bn * 128 + b_n;
    const uint32_t* Bpl = Bgl + (size_t)b_r * N + bn * 128 + b_n;

    // smem store offsets
    const int aoff = a_r * ASTR + a_c * 8;           // elems
    const int boff0 = (2 * b_r) * BSTR + b_n;        // elems (even k row)
    const int boff1 = boff0 + BSTR;                  // odd k row

    // ldmatrix lane addresses (byte offsets within a tile's buffer)
    const uint32_t sbAh = (uint32_t)__cvta_generic_to_shared(Ah);
    const uint32_t sbAl = (uint32_t)__cvta_generic_to_shared(Al);
    const uint32_t sbBh = (uint32_t)__cvta_generic_to_shared(Bh);
    const uint32_t sbBl = (uint32_t)__cvta_generic_to_shared(Bl);
    const uint32_t a_lane = (uint32_t)(((lane & 15) * ASTR + (lane >> 4) * 8) * 2);
    const int krow = (lane & 7) + ((lane >> 4) << 3);
    const int nsel = ((lane >> 3) & 1) << 3;
    const uint32_t b_lane = (uint32_t)((krow * BSTR + nsel) * 2);

    uint4 rah = *(const uint4*)Aph;
    uint4 ral = *(const uint4*)Apl;
    uint4 rbh = *(const uint4*)Bph;
    uint4 rbl = *(const uint4*)Bpl;

    // Stage 0
    {
        *(uint4*)&Ah[0][aoff] = rah;
        *(uint4*)&Al[0][aoff] = ral;
        uint2 lo = make_uint2(__byte_perm(rbh.x, rbh.y, 0x5410), __byte_perm(rbh.z, rbh.w, 0x5410));
        uint2 hi = make_uint2(__byte_perm(rbh.x, rbh.y, 0x7632), __byte_perm(rbh.z, rbh.w, 0x7632));
        *(uint2*)&Bh[0][boff0] = lo;
        *(uint2*)&Bh[0][boff1] = hi;
        lo = make_uint2(__byte_perm(rbl.x, rbl.y, 0x5410), __byte_perm(rbl.z, rbl.w, 0x5410));
        hi = make_uint2(__byte_perm(rbl.x, rbl.y, 0x7632), __byte_perm(rbl.z, rbl.w, 0x7632));
        *(uint2*)&Bl[0][boff0] = lo;
        *(uint2*)&Bl[0][boff1] = hi;
    }
    __syncthreads();

    float acc[4][4][4];
#pragma unroll
    for (int mt = 0; mt < 4; mt++)
#pragma unroll
        for (int nt = 0; nt < 4; nt++)
#pragma unroll
            for (int r = 0; r < 4; r++) acc[mt][nt][r] = 0.f;

    const int nst = K2 >> 3;
    for (int st = 0; st < nst; st++) {
        const int cur = st & 1;
        const bool more = (st + 1 < nst);
        if (more) {
            rah = *(const uint4*)(Aph + (st + 1) * 8);
            ral = *(const uint4*)(Apl + (st + 1) * 8);
            rbh = *(const uint4*)(Bph + (size_t)(st + 1) * 8 * N);
            rbl = *(const uint4*)(Bpl + (size_t)(st + 1) * 8 * N);
        }

        const uint32_t abh = sbAh + (uint32_t)(cur * 128 * ASTR * 2);
        const uint32_t abl = sbAl + (uint32_t)(cur * 128 * ASTR * 2);
        const uint32_t bbh = sbBh + (uint32_t)(cur * 16 * BSTR * 2);
        const uint32_t bbl = sbBl + (uint32_t)(cur * 16 * BSTR * 2);

        // B fragments: 2 ldmatrix.x4.trans per precision (covers 4 nt blocks)
        uint32_t bhf[4][2], blf[4][2];
#pragma unroll
        for (int p = 0; p < 2; p++) {
            const uint32_t off = b_lane + (uint32_t)((wn * 32 + p * 16) * 2);
            LDSM4T(bhf[2 * p][0], bhf[2 * p + 1][0], bhf[2 * p][1], bhf[2 * p + 1][1], bbh + off);
            LDSM4T(blf[2 * p][0], blf[2 * p + 1][0], blf[2 * p][1], blf[2 * p + 1][1], bbl + off);
        }

#pragma unroll
        for (int mt = 0; mt < 4; mt++) {
            const uint32_t off = a_lane + (uint32_t)((wm * 64 + mt * 16) * ASTR * 2);
            uint32_t ah0, ah1, ah2, ah3, al0, al1, al2, al3;
            LDSM4(ah0, ah1, ah2, ah3, abh + off);
            LDSM4(al0, al1, al2, al3, abl + off);
#pragma unroll
            for (int nt = 0; nt < 4; nt++) {
                MMA_BF16(acc[mt][nt], ah0, ah1, ah2, ah3, bhf[nt][0], bhf[nt][1]);
                MMA_BF16(acc[mt][nt], ah0, ah1, ah2, ah3, blf[nt][0], blf[nt][1]);
                MMA_BF16(acc[mt][nt], al0, al1, al2, al3, bhf[nt][0], bhf[nt][1]);
            }
        }

        if (more) {
            const int nxt = cur ^ 1;
            __syncthreads();
            *(uint4*)&Ah[nxt][aoff] = rah;
            *(uint4*)&Al[nxt][aoff] = ral;
            uint2 lo = make_uint2(__byte_perm(rbh.x, rbh.y, 0x5410), __byte_perm(rbh.z, rbh.w, 0x5410));
            uint2 hi = make_uint2(__byte_perm(rbh.x, rbh.y, 0x7632), __byte_perm(rbh.z, rbh.w, 0x7632));
            *(uint2*)&Bh[nxt][boff0] = lo;
            *(uint2*)&Bh[nxt][boff1] = hi;
            lo = make_uint2(__byte_perm(rbl.x, rbl.y, 0x5410), __byte_perm(rbl.z, rbl.w, 0x5410));
            hi = make_uint2(__byte_perm(rbl.x, rbl.y, 0x7632), __byte_perm(rbl.z, rbl.w, 0x7632));
            *(uint2*)&Bl[nxt][boff0] = lo;
            *(uint2*)&Bl[nxt][boff1] = hi;
            __syncthreads();
        }
    }

    // Epilogue
#pragma unroll
    for (int mt = 0; mt < 4; mt++) {
        const int row = bm * 128 + wm * 64 + mt * 16 + gid;
#pragma unroll
        for (int nt = 0; nt < 4; nt++) {
            const int col = bn * 128 + wn * 32 + nt * 8 + tig * 2;
            *(float2*)&C[(size_t)row * N + col] =
                make_float2(acc[mt][nt][0], acc[mt][nt][1]);
            *(float2*)&C[(size_t)(row + 8) * N + col] =
                make_float2(acc[mt][nt][2], acc[mt][nt][3]);
        }
    }
}

// ---------------------------------------------------------------------------
// RoPE
// ---------------------------------------------------------------------------
__global__ void rope_kernel(const float* __restrict__ cosb,
                            const float* __restrict__ sinb)
{
    const int total = S_LEN * (NH + NHK) * HD;
    int idx = blockIdx.x * blockDim.x + threadIdx.x;
    if (idx >= total) return;
    int d = idx % HD;
    int h = (idx / HD) % (NH + NHK);
    int s = idx / (HD * (NH + NHK));
    const float* row = g_qkv + (size_t)s * OP;
    float c  = cosb[s * HD + d];
    float sn = sinb[s * HD + d];
    if (h < NH) {
        int base = h * HD;
        float x = row[base + d];
        float r = (d < HD / 2) ? -row[base + d + HD / 2] : row[base + d - HD / 2];
        g_q[(size_t)s * (NH * HD) + h * HD + d] = x * c + r * sn;
    } else {
        int hk = h - NH;
        int base = KOFF + hk * HD;
        float x = row[base + d];
        float r = (d < HD / 2) ? -row[base + d + HD / 2] : row[base + d - HD / 2];
        g_k[(size_t)s * (NHK * HD) + hk * HD + d] = x * c + r * sn;
    }
}

// ---------------------------------------------------------------------------
// Pooling / gates / mask (unchanged)
// ---------------------------------------------------------------------------
__global__ void pool_kernel()
{
    int nb = blockIdx.x, hk = blockIdx.y, d = threadIdx.x;
    float ksum = 0.f, kmax = -3.0e38f, qsum = 0.f;
#pragma unroll 4
    for (int t = 0; t < BLK; t++) {
        const float* row = g_qkv + (size_t)(nb * BLK + t) * OP;
        float kv = row[KOFF + hk * HD + d];
        ksum += kv;
        kmax = fmaxf(kmax, kv);
#pragma unroll
        for (int g = 0; g < GQ; g++) qsum += row[(hk * GQ + g) * HD + d];
    }
    int bh = nb * NHK + hk;
    g_kpool[bh * (2 * HD) + d]      = ksum * (1.f / BLK);
    g_kpool[bh * (2 * HD) + HD + d] = kmax;
    g_qpool[bh * HD + d]            = qsum * (1.f / (BLK * GQ));
}

__global__ void gate_kernel(const float* __restrict__ gate_wq,
                            const float* __restrict__ gate_wk)
{
    int nb = blockIdx.x, hk = blockIdx.y, g = threadIdx.x;
    int bh = nb * NHK + hk;
    float qa = 0.f;
#pragma unroll 8
    for (int d = 0; d < HD; d++)
        qa += g_qpool[bh * HD + d] * gate_wq[d * GH + g];
    float ka = 0.f;
#pragma unroll 8
    for (int e = 0; e < 2 * HD; e++)
        ka += g_kpool[bh * (2 * HD) + e] * gate_wk[e * GH + g];
    g_qgate[bh * GH + g] = qa;
    g_kgate[bh * GH + g] = ka;
}

__global__ void mask_kernel()
{
    int qb = blockIdx.x, hk = blockIdx.y, kb = threadIdx.x;
    float l = -1e30f;
    if (kb <= qb) {
        float dot = 0.f;
#pragma unroll 8
        for (int g = 0; g < GH; g++)
            dot += g_qgate[(size_t)(qb * NHK + hk) * GH + g]
                 * g_kgate[(size_t)(kb * NHK + hk) * GH + g];
        l = dot * rsqrtf((float)GH);
    }
    float mx = l;
#pragma unroll
    for (int o = 16; o > 0; o >>= 1) mx = fmaxf(mx, __shfl_xor_sync(0xffffffffu, mx, o));
    float e = expf(l - mx);
    float sm = e;
#pragma unroll
    for (int o = 16; o > 0; o >>= 1) sm += __shfl_xor_sync(0xffffffffu, sm, o);
    float p = e / sm;
    int keep = ((p >= 0.03f) && (kb <= qb)) || (kb == qb);
    g_maskbuf[(hk * NB + qb) * NB + kb] = keep;
}

// ---------------------------------------------------------------------------
// Tensor-core block-sparse flash attention (bf16 hi/lo x3). Unchanged from R5
// except the epilogue now writes the packed bf16 hi/lo A operand for O-proj.
// ---------------------------------------------------------------------------
#define QSTR 104
#define VSTR 72

#define OFF_QH  0
#define OFF_QL  13312
#define OFF_KH(b) (26624  + (b) * 13312)
#define OFF_KL(b) (53248  + (b) * 13312)
#define OFF_VH(b) (79872  + (b) * 13824)
#define OFF_VL(b) (107520 + (b) * 13824)
#define OFF_BL  135168
#define ATTN_SMEM 135304

#define MMAB(CC, A, B0, B1)                                                    \
    asm volatile(                                                              \
        "mma.sync.aligned.m16n8k16.row.col.f32.bf16.bf16.f32 "                 \
        "{%0,%1,%2,%3}, {%4,%5,%6,%7}, {%8,%9}, {%0,%1,%2,%3};"                \
        : "+f"((CC)[0]), "+f"((CC)[1]), "+f"((CC)[2]), "+f"((CC)[3])           \
        : "r"((A)[0]), "r"((A)[1]), "r"((A)[2]), "r"((A)[3]), "r"(B0), "r"(B1))

__device__ __forceinline__ void load_kv_block(char* smem, int kb, int hk,
                                              int buf, int t2)
{
    uint16_t* Kh = (uint16_t*)(smem + OFF_KH(buf));
    uint16_t* Kl = (uint16_t*)(smem + OFF_KL(buf));
    uint16_t* Vh = (uint16_t*)(smem + OFF_VH(buf));
    uint16_t* Vl = (uint16_t*)(smem + OFF_VL(buf));

    for (int i = t2; i < 64 * 24; i += 128) {
        int c = i / 24, d4 = (i % 24) * 4;
        float4 v = *(const float4*)&g_k[(size_t)(kb * BLK + c) * (NHK * HD) + hk * HD + d4];
        ushort4 hi, lo;
        split1(v.x, hi.x, lo.x); split1(v.y, hi.y, lo.y);
        split1(v.z, hi.z, lo.z); split1(v.w, hi.w, lo.w);
        *(ushort4*)&Kh[c * QSTR + d4] = hi;
        *(ushort4*)&Kl[c * QSTR + d4] = lo;
    }
    for (int i = t2; i < 64 * 24; i += 128) {
        int t = i / 24, d4 = (i % 24) * 4;
        float4 v = *(const float4*)&g_qkv[(size_t)(kb * BLK + t) * OP + VOFF + hk * HD + d4];
        uint16_t h0, l0;
        split1(v.x, h0, l0); Vh[(d4 + 0) * VSTR + t] = h0; Vl[(d4 + 0) * VSTR + t] = l0;
        split1(v.y, h0, l0); Vh[(d4 + 1) * VSTR + t] = h0; Vl[(d4 + 1) * VSTR + t] = l0;
        split1(v.z, h0, l0); Vh[(d4 + 2) * VSTR + t] = h0; Vl[(d4 + 2) * VSTR + t] = l0;
        split1(v.w, h0, l0); Vh[(d4 + 3) * VSTR + t] = h0; Vl[(d4 + 3) * VSTR + t] = l0;
    }
}

__global__ __launch_bounds__(256, 1)
void attn_mma_kernel()
{
    extern __shared__ char smem[];
    const int qb = blockIdx.x, h = blockIdx.y, hk = h >> 2;
    const int tid = threadIdx.x;
    int* blist = (int*)(smem + OFF_BL);

    if (tid < 32) {
        int kb = tid;
        const int* mrow = g_maskbuf + (hk * NB + qb) * NB;
        int keep = (kb <= qb) && mrow[kb];
        unsigned bm = __ballot_sync(0xffffffffu, keep);
        if (keep) blist[__popc(bm & ((1u << kb) - 1u))] = kb;
        if (tid == 0) blist[32] = __popc(bm);
    }

    {
        const float scale = rsqrtf((float)HD);
        uint16_t* Qh = (uint16_t*)(smem + OFF_QH);
        uint16_t* Ql = (uint16_t*)(smem + OFF_QL);
        for (int i = tid; i < 64 * 24; i += 256) {
            int r = i / 24, d4 = (i % 24) * 4;
            float4 v = *(const float4*)&g_q[(size_t)(qb * BLK + r) * (NH * HD) + h * HD + d4];
            v.x *= scale; v.y *= scale; v.z *= scale; v.w *= scale;
            ushort4 hi, lo;
            split1(v.x, hi.x, lo.x); split1(v.y, hi.y, lo.y);
            split1(v.z, hi.z, lo.z); split1(v.w, hi.w, lo.w);
            *(ushort4*)&Qh[r * QSTR + d4] = hi;
            *(ushort4*)&Ql[r * QSTR + d4] = lo;
        }
    }
    __syncthreads();

    const int nblk = blist[32];
    const int lane = tid & 31, warp = tid >> 5;

    if (warp >= 4) {
        int t2 = tid - 128;
        if (nblk > 0) load_kv_block(smem, blist[0], hk, 0, t2);
        __syncthreads();
        for (int i = 0; i < nblk; i++) {
            if (i + 1 < nblk) load_kv_block(smem, blist[i + 1], hk, (i + 1) & 1, t2);
            __syncthreads();
        }
        return;
    }

    const int row0 = warp * 16;
    const int g    = lane & 7, quad = lane >> 3;
    const int gid  = lane >> 2, tig = lane & 3;
    const uint32_t sb = (uint32_t)__cvta_generic_to_shared(smem);

    uint32_t qfh[6][4], qfl[6][4];
    {
        int ar = row0 + g + ((quad & 1) << 3);
#pragma unroll
        for (int ks = 0; ks < 6; ks++) {
            uint32_t off = (uint32_t)(ar * QSTR + ks * 16 + ((quad & 2) << 2)) * 2u;
            LDSM4(qfh[ks][0], qfh[ks][1], qfh[ks][2], qfh[ks][3], sb + OFF_QH + off);
            LDSM4(qfl[ks][0], qfl[ks][1], qfl[ks][2], qfl[ks][3], sb + OFF_QL + off);
        }
    }

    float o[12][4];
#pragma unroll
    for (int dt = 0; dt < 12; dt++)
#pragma unroll
        for (int e = 0; e < 4; e++) o[dt][e] = 0.f;
    float m0 = -1e30f, m1 = -1e30f, l0 = 0.f, l1 = 0.f;

    __syncthreads();

    const int kr = g + ((quad >> 1) << 3);
    const int kd = (quad & 1) << 3;

    for (int i = 0; i < nblk; i++) {
        const int buf = i & 1;
        const int kb  = blist[i];
        const uint32_t khb = sb + OFF_KH(buf), klb = sb + OFF_KL(buf);
        const uint32_t vhb = sb + OFF_VH(buf), vlb = sb + OFF_VL(buf);

        float st[8][4];
#pragma unroll
        for (int nt = 0; nt < 8; nt++)
#pragma unroll
            for (int e = 0; e < 4; e++) st[nt][e] = 0.f;

#pragma unroll
        for (int ks = 0; ks < 6; ks++) {
#pragma unroll
            for (int ng = 0; ng < 4; ng++) {
                uint32_t off = (uint32_t)((ng * 16 + kr) * QSTR + ks * 16 + kd) * 2u;
                uint32_t b0, b1, b2, b3, c0, c1, c2, c3;
                LDSM4(b0, b1, b2, b3, khb + off);
                LDSM4(c0, c1, c2, c3, klb + off);
                MMAB(st[2 * ng],     qfh[ks], b0, b1);
                MMAB(st[2 * ng + 1], qfh[ks], b2, b3);
                MMAB(st[2 * ng],     qfh[ks], c0, c1);
                MMAB(st[2 * ng + 1], qfh[ks], c2, c3);
                MMAB(st[2 * ng],     qfl[ks], b0, b1);
                MMAB(st[2 * ng + 1], qfl[ks], b2, b3);
            }
        }

        if (kb == qb) {
            const int rA = row0 + gid, rB = rA + 8;
#pragma unroll
            for (int nt = 0; nt < 8; nt++) {
                int cb = nt * 8 + tig * 2;
                if (cb     > rA) st[nt][0] = -1e30f;
                if (cb + 1 > rA) st[nt][1] = -1e30f;
                if (cb     > rB) st[nt][2] = -1e30f;
                if (cb + 1 > rB) st[nt][3] = -1e30f;
            }
        }

        float mA = -1e30f, mB = -1e30f;
#pragma unroll
        for (int nt = 0; nt < 8; nt++) {
            mA = fmaxf(mA, fmaxf(st[nt][0], st[nt][1]));
            mB = fmaxf(mB, fmaxf(st[nt][2], st[nt][3]));
        }
        mA = fmaxf(mA, __shfl_xor_sync(0xffffffffu, mA, 1));
        mA = fmaxf(mA, __shfl_xor_sync(0xffffffffu, mA, 2));
        mB = fmaxf(mB, __shfl_xor_sync(0xffffffffu, mB, 1));
        mB = fmaxf(mB, __shfl_xor_sync(0xffffffffu, mB, 2));
        float nmA = fmaxf(m0, mA), nmB = fmaxf(m1, mB);
        float cA = __expf(m0 - nmA), cB = __expf(m1 - nmB);
        float sA = 0.f, sB = 0.f;
#pragma unroll
        for (int nt = 0; nt < 8; nt++) {
            st[nt][0] = __expf(st[nt][0] - nmA); sA += st[nt][0];
            st[nt][1] = __expf(st[nt][1] - nmA); sA += st[nt][1];
            st[nt][2] = __expf(st[nt][2] - nmB); sB += st[nt][2];
            st[nt][3] = __expf(st[nt][3] - nmB); sB += st[nt][3];
        }
        sA += __shfl_xor_sync(0xffffffffu, sA, 1);
        sA += __shfl_xor_sync(0xffffffffu, sA, 2);
        sB += __shfl_xor_sync(0xffffffffu, sB, 1);
        sB += __shfl_xor_sync(0xffffffffu, sB, 2);
        l0 = l0 * cA + sA; m0 = nmA;
        l1 = l1 * cB + sB; m1 = nmB;
#pragma unroll
        for (int dt = 0; dt < 12; dt++) {
            o[dt][0] *= cA; o[dt][1] *= cA;
            o[dt][2] *= cB; o[dt][3] *= cB;
        }

        uint32_t ph[4][4], pl[4][4];
#pragma unroll
        for (int j = 0; j < 4; j++) {
            ph[j][0] = split2(st[2 * j][0],     st[2 * j][1],     pl[j][0]);
            ph[j][1] = split2(st[2 * j][2],     st[2 * j][3],     pl[j][1]);
            ph[j][2] = split2(st[2 * j + 1][0], st[2 * j + 1][1], pl[j][2]);
            ph[j][3] = split2(st[2 * j + 1][2], st[2 * j + 1][3], pl[j][3]);
        }

#pragma unroll
        for (int dt = 0; dt < 12; dt++) {
            uint32_t off1 = (uint32_t)((dt * 8 + g) * VSTR + quad * 8) * 2u;
            uint32_t off2 = off1 + 64u;
            uint32_t vA0, vA1, vA2, vA3, vB0, vB1, vB2, vB3;
            uint32_t wA0, wA1, wA2, wA3, wB0, wB1, wB2, wB3;
            LDSM4(vA0, vA1, vA2, vA3, vhb + off1);
            LDSM4(vB0, vB1, vB2, vB3, vhb + off2);
            LDSM4(wA0, wA1, wA2, wA3, vlb + off1);
            LDSM4(wB0, wB1, wB2, wB3, vlb + off2);
            MMAB(o[dt], ph[0], vA0, vA1);
            MMAB(o[dt], ph[0], wA0, wA1);
            MMAB(o[dt], pl[0], vA0, vA1);
            MMAB(o[dt], ph[1], vA2, vA3);
            MMAB(o[dt], ph[1], wA2, wA3);
            MMAB(o[dt], pl[1], vA2, vA3);
            MMAB(o[dt], ph[2], vB0, vB1);
            MMAB(o[dt], ph[2], wB0, wB1);
            MMAB(o[dt], pl[2], vB0, vB1);
            MMAB(o[dt], ph[3], vB2, vB3);
            MMAB(o[dt], ph[3], wB2, wB3);
            MMAB(o[dt], pl[3], vB2, vB3);
        }

        __syncthreads();
    }

    // epilogue: write packed bf16 hi/lo A operand for the O projection
    const float iA = 1.f / l0, iB = 1.f / l1;
    const int rA = qb * BLK + row0 + gid;
#pragma unroll
    for (int dt = 0; dt < 12; dt++) {
        int k2 = (h * HD + dt * 8 + tig * 2) >> 1;
        uint32_t loA, loB;
        uint32_t hiA = split2(o[dt][0] * iA, o[dt][1] * iA, loA);
        uint32_t hiB = split2(o[dt][2] * iB, o[dt][3] * iB, loB);
        g_ah[(size_t)rA * K2H + k2]       = hiA;
        g_al[(size_t)rA * K2H + k2]       = loA;
        g_ah[(size_t)(rA + 8) * K2H + k2] = hiB;
        g_al[(size_t)(rA + 8) * K2H + k2] = loB;
    }
}

// ---------------------------------------------------------------------------
// Launch
// ---------------------------------------------------------------------------
extern "C" void kernel_launch(void* const* d_in, const int* in_sizes, int n_in,
                              void* d_out, int out_size)
{
    const float* hs      = (const float*)d_in[0];
    const float* cosb    = (const float*)d_in[1];
    const float* sinb    = (const float*)d_in[2];
    const float* qkv_w   = (const float*)d_in[3];
    const float* o_w     = (const float*)d_in[4];
    const float* gate_wq = (const float*)d_in[5];
    const float* gate_wk = (const float*)d_in[6];
    float* out = (float*)d_out;

    void *p_qkv, *p_ah, *p_al, *p_wqh, *p_wql, *p_woh, *p_wol;
    cudaGetSymbolAddress(&p_qkv, g_qkv);
    cudaGetSymbolAddress(&p_ah, g_ah);
    cudaGetSymbolAddress(&p_al, g_al);
    cudaGetSymbolAddress(&p_wqh, g_wqh);
    cudaGetSymbolAddress(&p_wql, g_wql);
    cudaGetSymbolAddress(&p_woh, g_woh);
    cudaGetSymbolAddress(&p_wol, g_wol);

    // 0. Pack operands into bf16 hi/lo
    {
        int totW1 = K2H * OP;
        packB_kernel<<<(totW1 + 255) / 256, 256>>>(
            qkv_w, (uint32_t*)p_wqh, (uint32_t*)p_wql, OP, totW1);
        int totW2 = K2H * HIDDEN;
        packB_kernel<<<(totW2 + 255) / 256, 256>>>(
            o_w, (uint32_t*)p_woh, (uint32_t*)p_wol, HIDDEN, totW2);
        int totA = S_LEN * K2H;
        packA_kernel<<<(totA + 255) / 256, 256>>>(
            hs, (uint32_t*)p_ah, (uint32_t*)p_al, totA);
    }

    // 1. QKV projection (bf16x3 tensor cores, ldmatrix)
    bf16x3_gemm<<<dim3(OP / 128, S_LEN / 128), 256>>>(
        (const uint32_t*)p_ah, (const uint32_t*)p_al,
        (const uint32_t*)p_wqh, (const uint32_t*)p_wql,
        (float*)p_qkv, S_LEN, OP, K2H);

    // 2. RoPE
    {
        int total = S_LEN * (NH + NHK) * HD;
        rope_kernel<<<(total + 255) / 256, 256>>>(cosb, sinb);
    }

    // 3. Pool + gate + mask
    pool_kernel<<<dim3(NB, NHK), HD>>>();
    gate_kernel<<<dim3(NB, NHK), GH>>>(gate_wq, gate_wk);
    mask_kernel<<<dim3(NB, NHK), 32>>>();

    // 4. Tensor-core block-sparse flash attention (writes packed O-proj A operand)
    cudaFuncSetAttribute(attn_mma_kernel,
                         cudaFuncAttributeMaxDynamicSharedMemorySize, ATTN_SMEM);
    attn_mma_kernel<<<dim3(NB, NH), 256, ATTN_SMEM>>>();

    // 5. Output projection (bf16x3 tensor cores, ldmatrix)
    bf16x3_gemm<<<dim3(HIDDEN / 128, S_LEN / 128), 256>>>(
        (const uint32_t*)p_ah, (const uint32_t*)p_al,
        (const uint32_t*)p_woh, (const uint32_t*)p_wol,
        out, S_LEN, HIDDEN, HIDDEN / 2);
}

// round 7
// speedup vs baseline: 1.0827x; 1.0827x over previous
#include <cuda_runtime.h>
#include <cuda_bf16.h>
#include <cstdint>
#include <math.h>

// ---------------------------------------------------------------------------
// Problem constants
// ---------------------------------------------------------------------------
#define S_LEN   2048
#define HIDDEN  3072
#define NH      32        // query heads
#define NHK     8         // kv heads
#define GQ      4         // H / HK
#define HD      96        // head dim
#define BLK     64        // attention block size
#define NB      32        // S / BLK
#define GH      128       // gate hidden
#define OP      4608      // H*D + 2*HK*D
#define KOFF    3072
#define VOFF    3840
#define K2H     (HIDDEN / 2)   // 1536 packed-k words

// ---------------------------------------------------------------------------
// Scratch (device globals; no allocation allowed)
// ---------------------------------------------------------------------------
__device__ float g_qkv [S_LEN * OP];          // raw qkv (pre-rope)
__device__ float g_q   [S_LEN * NH  * HD];    // roped q
__device__ float g_k   [S_LEN * NHK * HD];    // roped k
__device__ float g_qpool[NB * NHK * HD];
__device__ float g_kpool[NB * NHK * 2 * HD];
__device__ float g_qgate[NB * NHK * GH];
__device__ float g_kgate[NB * NHK * GH];
__device__ int   g_maskbuf[NHK * NB * NB];

// bf16 hi/lo packed operands (k-pairs packed into one uint32)
__device__ uint32_t g_ah [S_LEN * K2H];       // A hi (hs, then attn out)
__device__ uint32_t g_al [S_LEN * K2H];       // A lo
__device__ uint32_t g_wqh[K2H * OP];
__device__ uint32_t g_wql[K2H * OP];
__device__ uint32_t g_woh[K2H * HIDDEN];
__device__ uint32_t g_wol[K2H * HIDDEN];

// ---------------------------------------------------------------------------
// bf16 hi/lo split helpers
// ---------------------------------------------------------------------------
__device__ __forceinline__ void bsplit(float x, uint32_t& h, uint32_t& l)
{
    __nv_bfloat16 hb = __float2bfloat16(x);
    float hf = __bfloat162float(hb);
    __nv_bfloat16 lb = __float2bfloat16(x - hf);
    h = (uint32_t)__bfloat16_as_ushort(hb);
    l = (uint32_t)__bfloat16_as_ushort(lb);
}

__device__ __forceinline__ void split1(float x, uint16_t& h, uint16_t& l)
{
    __nv_bfloat16 hb = __float2bfloat16(x);
    h = __bfloat16_as_ushort(hb);
    l = __bfloat16_as_ushort(__float2bfloat16(x - __bfloat162float(hb)));
}

__device__ __forceinline__ uint32_t split2(float x, float y, uint32_t& lo)
{
    __nv_bfloat16 hx = __float2bfloat16(x), hy = __float2bfloat16(y);
    float rx = x - __bfloat162float(hx), ry = y - __bfloat162float(hy);
    __nv_bfloat16 lx = __float2bfloat16(rx), ly = __float2bfloat16(ry);
    lo = (uint32_t)__bfloat16_as_ushort(lx) | ((uint32_t)__bfloat16_as_ushort(ly) << 16);
    return (uint32_t)__bfloat16_as_ushort(hx) | ((uint32_t)__bfloat16_as_ushort(hy) << 16);
}

// Pack A (row-major M x K): word i = (x[2i], x[2i+1]) along k
__global__ void packA_kernel(const float* __restrict__ in,
                             uint32_t* __restrict__ hi, uint32_t* __restrict__ lo,
                             int total2)
{
    int i = blockIdx.x * blockDim.x + threadIdx.x;
    if (i >= total2) return;
    float2 v = ((const float2*)in)[i];
    uint32_t h0, l0, h1, l1;
    bsplit(v.x, h0, l0);
    bsplit(v.y, h1, l1);
    hi[i] = h0 | (h1 << 16);
    lo[i] = l0 | (l1 << 16);
}

// Pack B (row-major K x N): out[k2][n] = (B[2k2][n], B[2k2+1][n])
__global__ void packB_kernel(const float* __restrict__ in,
                             uint32_t* __restrict__ hi, uint32_t* __restrict__ lo,
                             int N, int total)
{
    int i = blockIdx.x * blockDim.x + threadIdx.x;
    if (i >= total) return;
    int k2 = i / N, n = i - k2 * N;
    float x0 = in[(size_t)(2 * k2) * N + n];
    float x1 = in[(size_t)(2 * k2 + 1) * N + n];
    uint32_t h0, l0, h1, l1;
    bsplit(x0, h0, l0);
    bsplit(x1, h1, l1);
    hi[i] = h0 | (h1 << 16);
    lo[i] = l0 | (l1 << 16);
}

// ---------------------------------------------------------------------------
// bf16x3 tensor-core GEMM (the proven R4 version: scalar-LDS fragments,
// padded uint32 smem). 128x128 tile, BK=16 (8 words), 256 threads,
// warp tile 64x32, 3 MMAs per k16 (hi*hi + hi*lo + lo*hi).
// ---------------------------------------------------------------------------
#define PADB 136

#define MMA_BF16(CC, A0, A1, A2, A3, B0, B1)                                   \
    asm volatile(                                                              \
        "mma.sync.aligned.m16n8k16.row.col.f32.bf16.bf16.f32 "                 \
        "{%0,%1,%2,%3}, {%4,%5,%6,%7}, {%8,%9}, {%0,%1,%2,%3};"                \
        : "+f"(CC[0]), "+f"(CC[1]), "+f"(CC[2]), "+f"(CC[3])                   \
        : "r"(A0), "r"(A1), "r"(A2), "r"(A3), "r"(B0), "r"(B1))

__global__ __launch_bounds__(256, 2)
void bf16x3_gemm(const uint32_t* __restrict__ Agh, const uint32_t* __restrict__ Agl,
                 const uint32_t* __restrict__ Bgh, const uint32_t* __restrict__ Bgl,
                 float* __restrict__ C, int M, int N, int K2)
{
    __shared__ __align__(16) uint32_t Ah[2][8][PADB], Al[2][8][PADB];
    __shared__ __align__(16) uint32_t Bh[2][8][PADB], Bl[2][8][PADB];

    const int tid  = threadIdx.x;
    const int bn   = blockIdx.x, bm = blockIdx.y;
    const int warp = tid >> 5,  lane = tid & 31;
    const int wm   = warp >> 2, wn   = warp & 3;
    const int gid  = lane >> 2, tig  = lane & 3;

    const int a_r = tid >> 1, a_c = (tid & 1) * 4;
    const int b_r = tid >> 5, b_c = (tid & 31) * 4;

    const uint32_t* Aph = Agh + (size_t)(bm * 128 + a_r) * K2 + a_c;
    const uint32_t* Apl = Agl + (size_t)(bm * 128 + a_r) * K2 + a_c;
    const uint32_t* Bph = Bgh + (size_t)b_r * N + bn * 128 + b_c;
    const uint32_t* Bpl = Bgl + (size_t)b_r * N + bn * 128 + b_c;

    uint4 rah = *(const uint4*)Aph;
    uint4 ral = *(const uint4*)Apl;
    uint4 rbh = *(const uint4*)Bph;
    uint4 rbl = *(const uint4*)Bpl;

    Ah[0][a_c + 0][a_r] = rah.x; Ah[0][a_c + 1][a_r] = rah.y;
    Ah[0][a_c + 2][a_r] = rah.z; Ah[0][a_c + 3][a_r] = rah.w;
    Al[0][a_c + 0][a_r] = ral.x; Al[0][a_c + 1][a_r] = ral.y;
    Al[0][a_c + 2][a_r] = ral.z; Al[0][a_c + 3][a_r] = ral.w;
    *(uint4*)&Bh[0][b_r][b_c] = rbh;
    *(uint4*)&Bl[0][b_r][b_c] = rbl;
    __syncthreads();

    float acc[4][4][4];
#pragma unroll
    for (int mt = 0; mt < 4; mt++)
#pragma unroll
        for (int nt = 0; nt < 4; nt++)
#pragma unroll
            for (int r = 0; r < 4; r++) acc[mt][nt][r] = 0.f;

    const int nst = K2 >> 3;
    for (int st = 0; st < nst; st++) {
        const int cur = st & 1;
        const bool more = (st + 1 < nst);
        if (more) {
            rah = *(const uint4*)(Aph + (st + 1) * 8);
            ral = *(const uint4*)(Apl + (st + 1) * 8);
            rbh = *(const uint4*)(Bph + (size_t)(st + 1) * 8 * N);
            rbl = *(const uint4*)(Bpl + (size_t)(st + 1) * 8 * N);
        }

        uint32_t bhf[4][2], blf[4][2];
#pragma unroll
        for (int nt = 0; nt < 4; nt++) {
            const int n0 = wn * 32 + nt * 8;
            bhf[nt][0] = Bh[cur][tig][n0 + gid];
            bhf[nt][1] = Bh[cur][tig + 4][n0 + gid];
            blf[nt][0] = Bl[cur][tig][n0 + gid];
            blf[nt][1] = Bl[cur][tig + 4][n0 + gid];
        }

#pragma unroll
        for (int mt = 0; mt < 4; mt++) {
            const int m0 = wm * 64 + mt * 16;
            uint32_t ah0 = Ah[cur][tig][m0 + gid];
            uint32_t ah1 = Ah[cur][tig][m0 + gid + 8];
            uint32_t ah2 = Ah[cur][tig + 4][m0 + gid];
            uint32_t ah3 = Ah[cur][tig + 4][m0 + gid + 8];
            uint32_t al0 = Al[cur][tig][m0 + gid];
            uint32_t al1 = Al[cur][tig][m0 + gid + 8];
            uint32_t al2 = Al[cur][tig + 4][m0 + gid];
            uint32_t al3 = Al[cur][tig + 4][m0 + gid + 8];
#pragma unroll
            for (int nt = 0; nt < 4; nt++) {
                MMA_BF16(acc[mt][nt], ah0, ah1, ah2, ah3, bhf[nt][0], bhf[nt][1]);
                MMA_BF16(acc[mt][nt], ah0, ah1, ah2, ah3, blf[nt][0], blf[nt][1]);
                MMA_BF16(acc[mt][nt], al0, al1, al2, al3, bhf[nt][0], bhf[nt][1]);
            }
        }

        if (more) {
            const int nxt = cur ^ 1;
            Ah[nxt][a_c + 0][a_r] = rah.x; Ah[nxt][a_c + 1][a_r] = rah.y;
            Ah[nxt][a_c + 2][a_r] = rah.z; Ah[nxt][a_c + 3][a_r] = rah.w;
            Al[nxt][a_c + 0][a_r] = ral.x; Al[nxt][a_c + 1][a_r] = ral.y;
            Al[nxt][a_c + 2][a_r] = ral.z; Al[nxt][a_c + 3][a_r] = ral.w;
            *(uint4*)&Bh[nxt][b_r][b_c] = rbh;
            *(uint4*)&Bl[nxt][b_r][b_c] = rbl;
            __syncthreads();
        }
    }

#pragma unroll
    for (int mt = 0; mt < 4; mt++) {
        const int row = bm * 128 + wm * 64 + mt * 16 + gid;
#pragma unroll
        for (int nt = 0; nt < 4; nt++) {
            const int col = bn * 128 + wn * 32 + nt * 8 + tig * 2;
            *(float2*)&C[(size_t)row * N + col] =
                make_float2(acc[mt][nt][0], acc[mt][nt][1]);
            *(float2*)&C[(size_t)(row + 8) * N + col] =
                make_float2(acc[mt][nt][2], acc[mt][nt][3]);
        }
    }
}

// ---------------------------------------------------------------------------
// RoPE
// ---------------------------------------------------------------------------
__global__ void rope_kernel(const float* __restrict__ cosb,
                            const float* __restrict__ sinb)
{
    const int total = S_LEN * (NH + NHK) * HD;
    int idx = blockIdx.x * blockDim.x + threadIdx.x;
    if (idx >= total) return;
    int d = idx % HD;
    int h = (idx / HD) % (NH + NHK);
    int s = idx / (HD * (NH + NHK));
    const float* row = g_qkv + (size_t)s * OP;
    float c  = cosb[s * HD + d];
    float sn = sinb[s * HD + d];
    if (h < NH) {
        int base = h * HD;
        float x = row[base + d];
        float r = (d < HD / 2) ? -row[base + d + HD / 2] : row[base + d - HD / 2];
        g_q[(size_t)s * (NH * HD) + h * HD + d] = x * c + r * sn;
    } else {
        int hk = h - NH;
        int base = KOFF + hk * HD;
        float x = row[base + d];
        float r = (d < HD / 2) ? -row[base + d + HD / 2] : row[base + d - HD / 2];
        g_k[(size_t)s * (NHK * HD) + hk * HD + d] = x * c + r * sn;
    }
}

// ---------------------------------------------------------------------------
// Pooling / gates / mask (unchanged)
// ---------------------------------------------------------------------------
__global__ void pool_kernel()
{
    int nb = blockIdx.x, hk = blockIdx.y, d = threadIdx.x;
    float ksum = 0.f, kmax = -3.0e38f, qsum = 0.f;
#pragma unroll 4
    for (int t = 0; t < BLK; t++) {
        const float* row = g_qkv + (size_t)(nb * BLK + t) * OP;
        float kv = row[KOFF + hk * HD + d];
        ksum += kv;
        kmax = fmaxf(kmax, kv);
#pragma unroll
        for (int g = 0; g < GQ; g++) qsum += row[(hk * GQ + g) * HD + d];
    }
    int bh = nb * NHK + hk;
    g_kpool[bh * (2 * HD) + d]      = ksum * (1.f / BLK);
    g_kpool[bh * (2 * HD) + HD + d] = kmax;
    g_qpool[bh * HD + d]            = qsum * (1.f / (BLK * GQ));
}

__global__ void gate_kernel(const float* __restrict__ gate_wq,
                            const float* __restrict__ gate_wk)
{
    int nb = blockIdx.x, hk = blockIdx.y, g = threadIdx.x;
    int bh = nb * NHK + hk;
    float qa = 0.f;
#pragma unroll 8
    for (int d = 0; d < HD; d++)
        qa += g_qpool[bh * HD + d] * gate_wq[d * GH + g];
    float ka = 0.f;
#pragma unroll 8
    for (int e = 0; e < 2 * HD; e++)
        ka += g_kpool[bh * (2 * HD) + e] * gate_wk[e * GH + g];
    g_qgate[bh * GH + g] = qa;
    g_kgate[bh * GH + g] = ka;
}

__global__ void mask_kernel()
{
    int qb = blockIdx.x, hk = blockIdx.y, kb = threadIdx.x;
    float l = -1e30f;
    if (kb <= qb) {
        float dot = 0.f;
#pragma unroll 8
        for (int g = 0; g < GH; g++)
            dot += g_qgate[(size_t)(qb * NHK + hk) * GH + g]
                 * g_kgate[(size_t)(kb * NHK + hk) * GH + g];
        l = dot * rsqrtf((float)GH);
    }
    float mx = l;
#pragma unroll
    for (int o = 16; o > 0; o >>= 1) mx = fmaxf(mx, __shfl_xor_sync(0xffffffffu, mx, o));
    float e = expf(l - mx);
    float sm = e;
#pragma unroll
    for (int o = 16; o > 0; o >>= 1) sm += __shfl_xor_sync(0xffffffffu, sm, o);
    float p = e / sm;
    int keep = ((p >= 0.03f) && (kb <= qb)) || (kb == qb);
    g_maskbuf[(hk * NB + qb) * NB + kb] = keep;
}

// ---------------------------------------------------------------------------
// Tensor-core block-sparse flash attention (bf16 hi/lo x3), fused epilogue:
// writes the packed bf16 hi/lo A operand for the O projection directly.
// ---------------------------------------------------------------------------
#define QSTR 104
#define VSTR 72

#define OFF_QH  0
#define OFF_QL  13312
#define OFF_KH(b) (26624  + (b) * 13312)
#define OFF_KL(b) (53248  + (b) * 13312)
#define OFF_VH(b) (79872  + (b) * 13824)
#define OFF_VL(b) (107520 + (b) * 13824)
#define OFF_BL  135168
#define ATTN_SMEM 135304

#define LDSM4(R0, R1, R2, R3, ADDR)                                            \
    asm volatile("ldmatrix.sync.aligned.m8n8.x4.shared.b16 {%0,%1,%2,%3}, [%4];" \
                 : "=r"(R0), "=r"(R1), "=r"(R2), "=r"(R3) : "r"(ADDR))

#define MMAB(CC, A, B0, B1)                                                    \
    asm volatile(                                                              \
        "mma.sync.aligned.m16n8k16.row.col.f32.bf16.bf16.f32 "                 \
        "{%0,%1,%2,%3}, {%4,%5,%6,%7}, {%8,%9}, {%0,%1,%2,%3};"                \
        : "+f"((CC)[0]), "+f"((CC)[1]), "+f"((CC)[2]), "+f"((CC)[3])           \
        : "r"((A)[0]), "r"((A)[1]), "r"((A)[2]), "r"((A)[3]), "r"(B0), "r"(B1))

__device__ __forceinline__ void load_kv_block(char* smem, int kb, int hk,
                                              int buf, int t2)
{
    uint16_t* Kh = (uint16_t*)(smem + OFF_KH(buf));
    uint16_t* Kl = (uint16_t*)(smem + OFF_KL(buf));
    uint16_t* Vh = (uint16_t*)(smem + OFF_VH(buf));
    uint16_t* Vl = (uint16_t*)(smem + OFF_VL(buf));

    for (int i = t2; i < 64 * 24; i += 128) {
        int c = i / 24, d4 = (i % 24) * 4;
        float4 v = *(const float4*)&g_k[(size_t)(kb * BLK + c) * (NHK * HD) + hk * HD + d4];
        ushort4 hi, lo;
        split1(v.x, hi.x, lo.x); split1(v.y, hi.y, lo.y);
        split1(v.z, hi.z, lo.z); split1(v.w, hi.w, lo.w);
        *(ushort4*)&Kh[c * QSTR + d4] = hi;
        *(ushort4*)&Kl[c * QSTR + d4] = lo;
    }
    for (int i = t2; i < 64 * 24; i += 128) {
        int t = i / 24, d4 = (i % 24) * 4;
        float4 v = *(const float4*)&g_qkv[(size_t)(kb * BLK + t) * OP + VOFF + hk * HD + d4];
        uint16_t h0, l0;
        split1(v.x, h0, l0); Vh[(d4 + 0) * VSTR + t] = h0; Vl[(d4 + 0) * VSTR + t] = l0;
        split1(v.y, h0, l0); Vh[(d4 + 1) * VSTR + t] = h0; Vl[(d4 + 1) * VSTR + t] = l0;
        split1(v.z, h0, l0); Vh[(d4 + 2) * VSTR + t] = h0; Vl[(d4 + 2) * VSTR + t] = l0;
        split1(v.w, h0, l0); Vh[(d4 + 3) * VSTR + t] = h0; Vl[(d4 + 3) * VSTR + t] = l0;
    }
}

__global__ __launch_bounds__(256, 1)
void attn_mma_kernel()
{
    extern __shared__ char smem[];
    const int qb = blockIdx.x, h = blockIdx.y, hk = h >> 2;
    const int tid = threadIdx.x;
    int* blist = (int*)(smem + OFF_BL);

    if (tid < 32) {
        int kb = tid;
        const int* mrow = g_maskbuf + (hk * NB + qb) * NB;
        int keep = (kb <= qb) && mrow[kb];
        unsigned bm = __ballot_sync(0xffffffffu, keep);
        if (keep) blist[__popc(bm & ((1u << kb) - 1u))] = kb;
        if (tid == 0) blist[32] = __popc(bm);
    }

    {
        const float scale = rsqrtf((float)HD);
        uint16_t* Qh = (uint16_t*)(smem + OFF_QH);
        uint16_t* Ql = (uint16_t*)(smem + OFF_QL);
        for (int i = tid; i < 64 * 24; i += 256) {
            int r = i / 24, d4 = (i % 24) * 4;
            float4 v = *(const float4*)&g_q[(size_t)(qb * BLK + r) * (NH * HD) + h * HD + d4];
            v.x *= scale; v.y *= scale; v.z *= scale; v.w *= scale;
            ushort4 hi, lo;
            split1(v.x, hi.x, lo.x); split1(v.y, hi.y, lo.y);
            split1(v.z, hi.z, lo.z); split1(v.w, hi.w, lo.w);
            *(ushort4*)&Qh[r * QSTR + d4] = hi;
            *(ushort4*)&Ql[r * QSTR + d4] = lo;
        }
    }
    __syncthreads();

    const int nblk = blist[32];
    const int lane = tid & 31, warp = tid >> 5;

    if (warp >= 4) {
        int t2 = tid - 128;
        if (nblk > 0) load_kv_block(smem, blist[0], hk, 0, t2);
        __syncthreads();
        for (int i = 0; i < nblk; i++) {
            if (i + 1 < nblk) load_kv_block(smem, blist[i + 1], hk, (i + 1) & 1, t2);
            __syncthreads();
        }
        return;
    }

    const int row0 = warp * 16;
    const int g    = lane & 7, quad = lane >> 3;
    const int gid  = lane >> 2, tig = lane & 3;
    const uint32_t sb = (uint32_t)__cvta_generic_to_shared(smem);

    uint32_t qfh[6][4], qfl[6][4];
    {
        int ar = row0 + g + ((quad & 1) << 3);
#pragma unroll
        for (int ks = 0; ks < 6; ks++) {
            uint32_t off = (uint32_t)(ar * QSTR + ks * 16 + ((quad & 2) << 2)) * 2u;
            LDSM4(qfh[ks][0], qfh[ks][1], qfh[ks][2], qfh[ks][3], sb + OFF_QH + off);
            LDSM4(qfl[ks][0], qfl[ks][1], qfl[ks][2], qfl[ks][3], sb + OFF_QL + off);
        }
    }

    float o[12][4];
#pragma unroll
    for (int dt = 0; dt < 12; dt++)
#pragma unroll
        for (int e = 0; e < 4; e++) o[dt][e] = 0.f;
    float m0 = -1e30f, m1 = -1e30f, l0 = 0.f, l1 = 0.f;

    __syncthreads();

    const int kr = g + ((quad >> 1) << 3);
    const int kd = (quad & 1) << 3;

    for (int i = 0; i < nblk; i++) {
        const int buf = i & 1;
        const int kb  = blist[i];
        const uint32_t khb = sb + OFF_KH(buf), klb = sb + OFF_KL(buf);
        const uint32_t vhb = sb + OFF_VH(buf), vlb = sb + OFF_VL(buf);

        float st[8][4];
#pragma unroll
        for (int nt = 0; nt < 8; nt++)
#pragma unroll
            for (int e = 0; e < 4; e++) st[nt][e] = 0.f;

#pragma unroll
        for (int ks = 0; ks < 6; ks++) {
#pragma unroll
            for (int ng = 0; ng < 4; ng++) {
                uint32_t off = (uint32_t)((ng * 16 + kr) * QSTR + ks * 16 + kd) * 2u;
                uint32_t b0, b1, b2, b3, c0, c1, c2, c3;
                LDSM4(b0, b1, b2, b3, khb + off);
                LDSM4(c0, c1, c2, c3, klb + off);
                MMAB(st[2 * ng],     qfh[ks], b0, b1);
                MMAB(st[2 * ng + 1], qfh[ks], b2, b3);
                MMAB(st[2 * ng],     qfh[ks], c0, c1);
                MMAB(st[2 * ng + 1], qfh[ks], c2, c3);
                MMAB(st[2 * ng],     qfl[ks], b0, b1);
                MMAB(st[2 * ng + 1], qfl[ks], b2, b3);
            }
        }

        if (kb == qb) {
            const int rA = row0 + gid, rB = rA + 8;
#pragma unroll
            for (int nt = 0; nt < 8; nt++) {
                int cb = nt * 8 + tig * 2;
                if (cb     > rA) st[nt][0] = -1e30f;
                if (cb + 1 > rA) st[nt][1] = -1e30f;
                if (cb     > rB) st[nt][2] = -1e30f;
                if (cb + 1 > rB) st[nt][3] = -1e30f;
            }
        }

        float mA = -1e30f, mB = -1e30f;
#pragma unroll
        for (int nt = 0; nt < 8; nt++) {
            mA = fmaxf(mA, fmaxf(st[nt][0], st[nt][1]));
            mB = fmaxf(mB, fmaxf(st[nt][2], st[nt][3]));
        }
        mA = fmaxf(mA, __shfl_xor_sync(0xffffffffu, mA, 1));
        mA = fmaxf(mA, __shfl_xor_sync(0xffffffffu, mA, 2));
        mB = fmaxf(mB, __shfl_xor_sync(0xffffffffu, mB, 1));
        mB = fmaxf(mB, __shfl_xor_sync(0xffffffffu, mB, 2));
        float nmA = fmaxf(m0, mA), nmB = fmaxf(m1, mB);
        float cA = __expf(m0 - nmA), cB = __expf(m1 - nmB);
        float sA = 0.f, sB = 0.f;
#pragma unroll
        for (int nt = 0; nt < 8; nt++) {
            st[nt][0] = __expf(st[nt][0] - nmA); sA += st[nt][0];
            st[nt][1] = __expf(st[nt][1] - nmA); sA += st[nt][1];
            st[nt][2] = __expf(st[nt][2] - nmB); sB += st[nt][2];
            st[nt][3] = __expf(st[nt][3] - nmB); sB += st[nt][3];
        }
        sA += __shfl_xor_sync(0xffffffffu, sA, 1);
        sA += __shfl_xor_sync(0xffffffffu, sA, 2);
        sB += __shfl_xor_sync(0xffffffffu, sB, 1);
        sB += __shfl_xor_sync(0xffffffffu, sB, 2);
        l0 = l0 * cA + sA; m0 = nmA;
        l1 = l1 * cB + sB; m1 = nmB;
#pragma unroll
        for (int dt = 0; dt < 12; dt++) {
            o[dt][0] *= cA; o[dt][1] *= cA;
            o[dt][2] *= cB; o[dt][3] *= cB;
        }

        uint32_t ph[4][4], pl[4][4];
#pragma unroll
        for (int j = 0; j < 4; j++) {
            ph[j][0] = split2(st[2 * j][0],     st[2 * j][1],     pl[j][0]);
            ph[j][1] = split2(st[2 * j][2],     st[2 * j][3],     pl[j][1]);
            ph[j][2] = split2(st[2 * j + 1][0], st[2 * j + 1][1], pl[j][2]);
            ph[j][3] = split2(st[2 * j + 1][2], st[2 * j + 1][3], pl[j][3]);
        }

#pragma unroll
        for (int dt = 0; dt < 12; dt++) {
            uint32_t off1 = (uint32_t)((dt * 8 + g) * VSTR + quad * 8) * 2u;
            uint32_t off2 = off1 + 64u;
            uint32_t vA0, vA1, vA2, vA3, vB0, vB1, vB2, vB3;
            uint32_t wA0, wA1, wA2, wA3, wB0, wB1, wB2, wB3;
            LDSM4(vA0, vA1, vA2, vA3, vhb + off1);
            LDSM4(vB0, vB1, vB2, vB3, vhb + off2);
            LDSM4(wA0, wA1, wA2, wA3, vlb + off1);
            LDSM4(wB0, wB1, wB2, wB3, vlb + off2);
            MMAB(o[dt], ph[0], vA0, vA1);
            MMAB(o[dt], ph[0], wA0, wA1);
            MMAB(o[dt], pl[0], vA0, vA1);
            MMAB(o[dt], ph[1], vA2, vA3);
            MMAB(o[dt], ph[1], wA2, wA3);
            MMAB(o[dt], pl[1], vA2, vA3);
            MMAB(o[dt], ph[2], vB0, vB1);
            MMAB(o[dt], ph[2], wB0, wB1);
            MMAB(o[dt], pl[2], vB0, vB1);
            MMAB(o[dt], ph[3], vB2, vB3);
            MMAB(o[dt], ph[3], wB2, wB3);
            MMAB(o[dt], pl[3], vB2, vB3);
        }

        __syncthreads();
    }

    // epilogue: write packed bf16 hi/lo A operand for the O projection
    const float iA = 1.f / l0, iB = 1.f / l1;
    const int rA = qb * BLK + row0 + gid;
#pragma unroll
    for (int dt = 0; dt < 12; dt++) {
        int k2 = (h * HD + dt * 8 + tig * 2) >> 1;
        uint32_t loA, loB;
        uint32_t hiA = split2(o[dt][0] * iA, o[dt][1] * iA, loA);
        uint32_t hiB = split2(o[dt][2] * iB, o[dt][3] * iB, loB);
        g_ah[(size_t)rA * K2H + k2]       = hiA;
        g_al[(size_t)rA * K2H + k2]       = loA;
        g_ah[(size_t)(rA + 8) * K2H + k2] = hiB;
        g_al[(size_t)(rA + 8) * K2H + k2] = loB;
    }
}

// ---------------------------------------------------------------------------
// Launch
// ---------------------------------------------------------------------------
extern "C" void kernel_launch(void* const* d_in, const int* in_sizes, int n_in,
                              void* d_out, int out_size)
{
    const float* hs      = (const float*)d_in[0];
    const float* cosb    = (const float*)d_in[1];
    const float* sinb    = (const float*)d_in[2];
    const float* qkv_w   = (const float*)d_in[3];
    const float* o_w     = (const float*)d_in[4];
    const float* gate_wq = (const float*)d_in[5];
    const float* gate_wk = (const float*)d_in[6];
    float* out = (float*)d_out;

    void *p_qkv, *p_ah, *p_al, *p_wqh, *p_wql, *p_woh, *p_wol;
    cudaGetSymbolAddress(&p_qkv, g_qkv);
    cudaGetSymbolAddress(&p_ah, g_ah);
    cudaGetSymbolAddress(&p_al, g_al);
    cudaGetSymbolAddress(&p_wqh, g_wqh);
    cudaGetSymbolAddress(&p_wql, g_wql);
    cudaGetSymbolAddress(&p_woh, g_woh);
    cudaGetSymbolAddress(&p_wol, g_wol);

    // 0. Pack operands into bf16 hi/lo
    {
        int totW1 = K2H * OP;
        packB_kernel<<<(totW1 + 255) / 256, 256>>>(
            qkv_w, (uint32_t*)p_wqh, (uint32_t*)p_wql, OP, totW1);
        int totW2 = K2H * HIDDEN;
        packB_kernel<<<(totW2 + 255) / 256, 256>>>(
            o_w, (uint32_t*)p_woh, (uint32_t*)p_wol, HIDDEN, totW2);
        int totA = S_LEN * K2H;
        packA_kernel<<<(totA + 255) / 256, 256>>>(
            hs, (uint32_t*)p_ah, (uint32_t*)p_al, totA);
    }

    // 1. QKV projection (bf16x3 tensor cores)
    bf16x3_gemm<<<dim3(OP / 128, S_LEN / 128), 256>>>(
        (const uint32_t*)p_ah, (const uint32_t*)p_al,
        (const uint32_t*)p_wqh, (const uint32_t*)p_wql,
        (float*)p_qkv, S_LEN, OP, K2H);

    // 2. RoPE
    {
        int total = S_LEN * (NH + NHK) * HD;
        rope_kernel<<<(total + 255) / 256, 256>>>(cosb, sinb);
    }

    // 3. Pool + gate + mask
    pool_kernel<<<dim3(NB, NHK), HD>>>();
    gate_kernel<<<dim3(NB, NHK), GH>>>(gate_wq, gate_wk);
    mask_kernel<<<dim3(NB, NHK), 32>>>();

    // 4. Tensor-core block-sparse flash attention (fused O-proj operand pack)
    cudaFuncSetAttribute(attn_mma_kernel,
                         cudaFuncAttributeMaxDynamicSharedMemorySize, ATTN_SMEM);
    attn_mma_kernel<<<dim3(NB, NH), 256, ATTN_SMEM>>>();

    // 5. Output projection (bf16x3 tensor cores)
    bf16x3_gemm<<<dim3(HIDDEN / 128, S_LEN / 128), 256>>>(
        (const uint32_t*)p_ah, (const uint32_t*)p_al,
        (const uint32_t*)p_woh, (const uint32_t*)p_wol,
        out, S_LEN, HIDDEN, HIDDEN / 2);
}